// round 1
// baseline (speedup 1.0000x reference)
#include <cuda_runtime.h>
#include <math.h>

#define BB 4
#define SS 2048
#define DD 128
#define EPSV 1e-5f

// scratch (no allocations allowed)
__device__ float g_qnorm[BB * SS];
__device__ float g_knorm[BB * SS];

// ---------------------------------------------------------------------------
// Kernel 1: row norms ||q||^2, ||k||^2. One warp per row, float4 loads.
// ---------------------------------------------------------------------------
__global__ __launch_bounds__(256) void norms_kernel(const float* __restrict__ q,
                                                    const float* __restrict__ k) {
    int warp = (blockIdx.x * blockDim.x + threadIdx.x) >> 5;
    int lane = threadIdx.x & 31;
    const int R = BB * SS;
    if (warp >= 2 * R) return;
    const float* src = (warp < R) ? (q + (size_t)warp * DD)
                                  : (k + (size_t)(warp - R) * DD);
    float4 v = ((const float4*)src)[lane];
    float s = v.x * v.x + v.y * v.y + v.z * v.z + v.w * v.w;
#pragma unroll
    for (int o = 16; o; o >>= 1) s += __shfl_xor_sync(0xffffffffu, s, o);
    if (lane == 0) {
        if (warp < R) g_qnorm[warp] = s;
        else          g_knorm[warp - R] = s;
    }
}

// ---------------------------------------------------------------------------
// Kernel 2: scores[b,s,t] = -softplus(beta)*dist(q_s,k_t) - bias
// 64x64 tile per block, D split into 2 chunks of 64 to stay < 48KB smem.
// Strided 4x4 register tiling: thread (tx,ty) owns rows {ty+16i}, cols {tx+16j}
// -> all shared loads conflict-free, all global stores coalesced.
// ---------------------------------------------------------------------------
__global__ __launch_bounds__(256) void scores_kernel(const float* __restrict__ q,
                                                     const float* __restrict__ k,
                                                     const float* __restrict__ cp,
                                                     const float* __restrict__ betap,
                                                     const float* __restrict__ biasp,
                                                     float* __restrict__ W) {
    __shared__ float Qs[64][64];      // 16 KB
    __shared__ float KsT[64][65];     // 16.25 KB (padded: conflict-free)

    const int b = blockIdx.z;
    const int row0 = blockIdx.y * 64, col0 = blockIdx.x * 64;
    const float* qb = q + ((size_t)b * SS + row0) * DD;
    const float* kb = k + ((size_t)b * SS + col0) * DD;
    const int tid = threadIdx.x;
    const int tx = tid & 15, ty = tid >> 4;

    float acc[4][4] = {};

    for (int dch = 0; dch < DD; dch += 64) {
        // load Q chunk [64 rows x 64 d] and K chunk transposed [64 d x 64 cols]
        for (int i = tid; i < 64 * 64; i += 256) {
            int r = i >> 6, dd = i & 63;
            Qs[r][dd] = qb[r * DD + dch + dd];     // coalesced
            KsT[dd][r] = kb[r * DD + dch + dd];    // coalesced read, cf write
        }
        __syncthreads();
#pragma unroll 8
        for (int kk = 0; kk < 64; kk++) {
            float a[4], bv[4];
#pragma unroll
            for (int i = 0; i < 4; i++) a[i] = Qs[ty + 16 * i][kk];   // broadcast
#pragma unroll
            for (int j = 0; j < 4; j++) bv[j] = KsT[kk][tx + 16 * j]; // cf
#pragma unroll
            for (int i = 0; i < 4; i++)
#pragma unroll
                for (int j = 0; j < 4; j++) acc[i][j] += a[i] * bv[j];
        }
        __syncthreads();
    }

    // epilogue: Poincare distance -> attention score
    const float c = *cp;
    const float sqrtc = sqrtf(c);
    const float beta = *betap;
    const float bias = *biasp;
    const float bp = fmaxf(beta, 0.f) + log1pf(expf(-fabsf(beta)));  // softplus

#pragma unroll
    for (int i = 0; i < 4; i++) {
        const int r = row0 + ty + 16 * i;
        const float qn = g_qnorm[b * SS + r];
        const float one_m_cqn = 1.f - c * qn;
        float* wrow = W + ((size_t)b * SS + r) * SS + col0;
#pragma unroll
        for (int j = 0; j < 4; j++) {
            const int cc = col0 + tx + 16 * j;
            const float kn = g_knorm[b * SS + cc];
            const float diff = qn - 2.f * acc[i][j] + kn;
            const float denom = one_m_cqn * (1.f - c * kn);
            const float arg = 1.f + 2.f * c * diff / fmaxf(denom, EPSV);
            const float dist = acoshf(fmaxf(arg, 1.f + EPSV)) / sqrtc;
            wrow[tx + 16 * j] = -bp * dist - bias;   // coalesced
        }
    }
}

// ---------------------------------------------------------------------------
// Kernel 3: in-place row softmax. One block per row, row held in registers.
// ---------------------------------------------------------------------------
__global__ __launch_bounds__(256) void softmax_kernel(float* __restrict__ W) {
    __shared__ float red[256];
    const int r = blockIdx.x;                  // 0 .. B*S-1
    float* wr = W + (size_t)r * SS;
    const int tid = threadIdx.x;

    float vals[8];
    float m = -INFINITY;
#pragma unroll
    for (int i = 0; i < 8; i++) {
        float x = wr[tid + 256 * i];
        vals[i] = x;
        m = fmaxf(m, x);
    }
    red[tid] = m;
    __syncthreads();
    for (int s2 = 128; s2; s2 >>= 1) {
        if (tid < s2) red[tid] = fmaxf(red[tid], red[tid + s2]);
        __syncthreads();
    }
    m = red[0];
    __syncthreads();

    float sum = 0.f;
#pragma unroll
    for (int i = 0; i < 8; i++) {
        vals[i] = expf(vals[i] - m);
        sum += vals[i];
    }
    red[tid] = sum;
    __syncthreads();
    for (int s2 = 128; s2; s2 >>= 1) {
        if (tid < s2) red[tid] += red[tid + s2];
        __syncthreads();
    }
    const float inv = 1.f / red[0];

#pragma unroll
    for (int i = 0; i < 8; i++) wr[tid + 256 * i] = vals[i] * inv;
}

// ---------------------------------------------------------------------------
// Kernel 4: out = expmap0( W @ v_tangent ). 32 rows x full D=128 per block.
// Thread (tx:32, ty:8) owns rows {ty+8i}, cols {tx+32j}. Warp ty owns 4 full
// rows -> exp-map row norm via shuffle reduce, fused epilogue.
// ---------------------------------------------------------------------------
__global__ __launch_bounds__(256) void av_kernel(const float* __restrict__ W,
                                                 const float* __restrict__ v,
                                                 const float* __restrict__ cp,
                                                 float* __restrict__ out) {
    __shared__ float Ws[32][64];    // 8 KB
    __shared__ float Vs[64][128];   // 32 KB

    const int b = blockIdx.z;
    const int row0 = blockIdx.y * 32;
    const int tid = threadIdx.x;
    const int tx = tid & 31, ty = tid >> 5;

    const float* wb = W + ((size_t)b * SS + row0) * SS;
    const float* vb = v + (size_t)b * SS * DD;

    float acc[4][4] = {};

    for (int t0 = 0; t0 < SS; t0 += 64) {
        for (int i = tid; i < 32 * 64; i += 256) {
            int r = i >> 6, t = i & 63;
            Ws[r][t] = wb[(size_t)r * SS + t0 + t];   // coalesced
        }
        for (int i = tid; i < 64 * 128; i += 256) {
            int t = i >> 7, d = i & 127;
            Vs[t][d] = vb[(t0 + t) * DD + d];         // coalesced
        }
        __syncthreads();
#pragma unroll 8
        for (int t = 0; t < 64; t++) {
            float a[4], bv[4];
#pragma unroll
            for (int i = 0; i < 4; i++) a[i] = Ws[ty + 8 * i][t];     // broadcast
#pragma unroll
            for (int j = 0; j < 4; j++) bv[j] = Vs[t][tx + 32 * j];   // cf
#pragma unroll
            for (int i = 0; i < 4; i++)
#pragma unroll
                for (int j = 0; j < 4; j++) acc[i][j] += a[i] * bv[j];
        }
        __syncthreads();
    }

    // fused exp-map at origin
    const float c = *cp;
    const float sqrtc = sqrtf(c);
#pragma unroll
    for (int i = 0; i < 4; i++) {
        float ns = 0.f;
#pragma unroll
        for (int j = 0; j < 4; j++) ns += acc[i][j] * acc[i][j];
#pragma unroll
        for (int o = 16; o; o >>= 1) ns += __shfl_xor_sync(0xffffffffu, ns, o);
        const float vn = fmaxf(sqrtf(ns), EPSV);
        const float scale = tanhf(sqrtc * vn) / (sqrtc * vn);
        const int r = row0 + ty + 8 * i;
        float* orow = out + ((size_t)b * SS + r) * DD;
#pragma unroll
        for (int j = 0; j < 4; j++) orow[tx + 32 * j] = acc[i][j] * scale;
    }
}

// ---------------------------------------------------------------------------
extern "C" void kernel_launch(void* const* d_in, const int* in_sizes, int n_in,
                              void* d_out, int out_size) {
    const float* q    = (const float*)d_in[0];
    const float* k    = (const float*)d_in[1];
    const float* v    = (const float*)d_in[2];
    const float* c    = (const float*)d_in[3];
    const float* beta = (const float*)d_in[4];
    const float* bias = (const float*)d_in[5];

    float* out = (float*)d_out;                    // output_hyperbolic (B,S,D)
    float* W   = out + (size_t)BB * SS * DD;       // attention_weights (B,S,S)

    // 1) row norms: 2*B*S warps
    norms_kernel<<<(2 * BB * SS * 32 + 255) / 256, 256>>>(q, k);

    // 2) raw scores into W
    scores_kernel<<<dim3(SS / 64, SS / 64, BB), 256>>>(q, k, c, beta, bias, W);

    // 3) in-place row softmax
    softmax_kernel<<<BB * SS, 256>>>(W);

    // 4) AV GEMM + fused exp-map
    av_kernel<<<dim3(1, SS / 32, BB), 256>>>(W, v, c, out);
}